// round 16
// baseline (speedup 1.0000x reference)
#include <cuda_runtime.h>
#include <cuda_bf16.h>
#include <math.h>
#include <stdint.h>

// ---------------- problem constants ----------------
#define D        1024
#define E        8
#define MOED     2048
#define T_TOK    8192
#define MAXROWS  16384
#define PADROWS  (MAXROWS + 256)
#define MAXCNT   4096

#define BK       16
#define ARS      48
#define BRS      272
#define AH_OFF   0
#define AL_OFF   6144
#define BH_OFF   12288
#define BL_OFF   16640
#define STAGE    20992
#define SM_G1    (3 * STAGE)   // gemm1: 3-stage (R15-proven)
#define SM_G2    (4 * STAGE)   // gemm2: 4-stage, barrier every 2 stages

// ---------------- device scratch (~238 MB total; proven safe) ----------
__device__ int   g_count[E];
__device__ int   g_offset[E];
__device__ int   g_tokens[E][MAXROWS];
__device__ float g_weights[E][MAXROWS];
__device__ __align__(256) __nv_bfloat16 g_x_hi[(size_t)T_TOK * D];
__device__ __align__(256) __nv_bfloat16 g_x_lo[(size_t)T_TOK * D];
__device__ __align__(256) __nv_bfloat16 g_hid_hi[(size_t)PADROWS * MOED];
__device__ __align__(256) __nv_bfloat16 g_hid_lo[(size_t)PADROWS * MOED];
__device__ __align__(256) __nv_bfloat16 g_w2_hi[(size_t)E * MOED * D];
__device__ __align__(256) __nv_bfloat16 g_w2_lo[(size_t)E * MOED * D];

// ---------------- helpers ----------------
__device__ __forceinline__ uint32_t smem_u32(const void* p) {
    uint32_t a;
    asm("{ .reg .u64 t; cvta.to.shared.u64 t, %1; cvt.u32.u64 %0, t; }" : "=r"(a) : "l"(p));
    return a;
}
__device__ __forceinline__ void cpasync16(uint32_t s, const void* g) {
    asm volatile("cp.async.cg.shared.global [%0], [%1], 16;" :: "r"(s), "l"(g));
}
#define CP_COMMIT() asm volatile("cp.async.commit_group;" ::: "memory")
#define CP_WAIT0()  asm volatile("cp.async.wait_group 0;"  ::: "memory")
#define CP_WAIT1()  asm volatile("cp.async.wait_group 1;"  ::: "memory")

__device__ __forceinline__ void ldsm4(uint32_t* r, uint32_t addr) {
    asm volatile("ldmatrix.sync.aligned.m8n8.x4.shared.b16 {%0,%1,%2,%3}, [%4];"
        : "=r"(r[0]), "=r"(r[1]), "=r"(r[2]), "=r"(r[3]) : "r"(addr));
}
__device__ __forceinline__ void ldsm4t(uint32_t* r, uint32_t addr) {
    asm volatile("ldmatrix.sync.aligned.m8n8.x4.trans.shared.b16 {%0,%1,%2,%3}, [%4];"
        : "=r"(r[0]), "=r"(r[1]), "=r"(r[2]), "=r"(r[3]) : "r"(addr));
}
__device__ __forceinline__ void mma16816(float* c, const uint32_t* a, uint32_t b0, uint32_t b1) {
    asm volatile("mma.sync.aligned.m16n8k16.row.col.f32.bf16.bf16.f32 "
        "{%0,%1,%2,%3}, {%4,%5,%6,%7}, {%8,%9}, {%0,%1,%2,%3};"
        : "+f"(c[0]), "+f"(c[1]), "+f"(c[2]), "+f"(c[3])
        : "r"(a[0]), "r"(a[1]), "r"(a[2]), "r"(a[3]), "r"(b0), "r"(b1));
}
__device__ __forceinline__ uint32_t pack2(float a, float b, uint32_t& lo) {
    __nv_bfloat16 ha = __float2bfloat16(a);
    __nv_bfloat16 hb = __float2bfloat16(b);
    __nv_bfloat16 la = __float2bfloat16(a - __bfloat162float(ha));
    __nv_bfloat16 lb = __float2bfloat16(b - __bfloat162float(hb));
    lo = (uint32_t)__bfloat16_as_ushort(la) | ((uint32_t)__bfloat16_as_ushort(lb) << 16);
    return (uint32_t)__bfloat16_as_ushort(ha) | ((uint32_t)__bfloat16_as_ushort(hb) << 16);
}
__device__ __forceinline__ void cvt8(float4 v0, float4 v1, uint4& hi, uint4& lo) {
    uint32_t l0, l1, l2, l3;
    uint32_t h0 = pack2(v0.x, v0.y, l0);
    uint32_t h1 = pack2(v0.z, v0.w, l1);
    uint32_t h2 = pack2(v1.x, v1.y, l2);
    uint32_t h3 = pack2(v1.z, v1.w, l3);
    hi = make_uint4(h0, h1, h2, h3);
    lo = make_uint4(l0, l1, l2, l3);
}

// ---------------- init ----------------
__global__ void init_kernel(float* __restrict__ out, int n) {
    int i = blockIdx.x * blockDim.x + threadIdx.x;
    if (i < E) g_count[i] = 0;
    for (; i < n; i += gridDim.x * blockDim.x) out[i] = 0.0f;
}

// ---------------- w2 split ----------------
__global__ void w2split_kernel(const float* __restrict__ w) {
    size_t i = ((size_t)blockIdx.x * blockDim.x + threadIdx.x) * 8;
    float4 v0 = *reinterpret_cast<const float4*>(w + i);
    float4 v1 = *reinterpret_cast<const float4*>(w + i + 4);
    uint4 hi, lo;
    cvt8(v0, v1, hi, lo);
    *reinterpret_cast<uint4*>(g_w2_hi + i) = hi;
    *reinterpret_cast<uint4*>(g_w2_lo + i) = lo;
}

// ---------------- fused router + x split (R13-proven) ----------
__global__ void router_kernel(const float* __restrict__ x,
                              const float* __restrict__ router, int T) {
    __shared__ float s_r[D * E];
    int tid = threadIdx.x;
    for (int i = tid; i < D * E; i += 256) s_r[i] = router[i];
    __syncthreads();

    int warp = tid >> 5, lane = tid & 31;
    int t = blockIdx.x * 8 + warp;
    if (t >= T) return;

    const float4* xr = reinterpret_cast<const float4*>(x + (size_t)t * D);
    uint2* dh = reinterpret_cast<uint2*>(g_x_hi + (size_t)t * D);
    uint2* dl = reinterpret_cast<uint2*>(g_x_lo + (size_t)t * D);

    float acc[8];
    #pragma unroll
    for (int e = 0; e < 8; e++) acc[e] = 0.0f;

    #pragma unroll
    for (int i = 0; i < 8; i++) {
        int idx = i * 32 + lane;
        float4 v = xr[idx];
        uint32_t lo0, lo1;
        uint32_t h0 = pack2(v.x, v.y, lo0);
        uint32_t h1 = pack2(v.z, v.w, lo1);
        dh[idx] = make_uint2(h0, h1);
        dl[idx] = make_uint2(lo0, lo1);
        int k0 = idx * 4;
        float xv[4] = {v.x, v.y, v.z, v.w};
        #pragma unroll
        for (int j = 0; j < 4; j++) {
            const float4* r4 = reinterpret_cast<const float4*>(s_r + (k0 + j) * E);
            float4 r0 = r4[0], r1 = r4[1];
            acc[0] = fmaf(xv[j], r0.x, acc[0]);
            acc[1] = fmaf(xv[j], r0.y, acc[1]);
            acc[2] = fmaf(xv[j], r0.z, acc[2]);
            acc[3] = fmaf(xv[j], r0.w, acc[3]);
            acc[4] = fmaf(xv[j], r1.x, acc[4]);
            acc[5] = fmaf(xv[j], r1.y, acc[5]);
            acc[6] = fmaf(xv[j], r1.z, acc[6]);
            acc[7] = fmaf(xv[j], r1.w, acc[7]);
        }
    }
    #pragma unroll
    for (int e = 0; e < 8; e++) {
        #pragma unroll
        for (int s = 16; s > 0; s >>= 1)
            acc[e] += __shfl_xor_sync(0xFFFFFFFFu, acc[e], s);
    }
    if (lane == 0) {
        int e0 = 0; float l0 = acc[0];
        #pragma unroll
        for (int i = 1; i < E; i++) if (acc[i] > l0) { l0 = acc[i]; e0 = i; }
        int e1 = -1; float l1 = -INFINITY;
        #pragma unroll
        for (int i = 0; i < E; i++) {
            if (i == e0) continue;
            if (acc[i] > l1) { l1 = acc[i]; e1 = i; }
        }
        float w0 = 1.0f / (1.0f + expf(l1 - l0));
        float w1 = 1.0f - w0;
        int s0 = atomicAdd(&g_count[e0], 1);
        g_tokens[e0][s0]  = t;
        g_weights[e0][s0] = w0;
        int s1 = atomicAdd(&g_count[e1], 1);
        g_tokens[e1][s1]  = t;
        g_weights[e1][s1] = w1;
    }
}

__global__ void offsets_kernel() {
    if (threadIdx.x == 0) {
        int s = 0;
        #pragma unroll
        for (int i = 0; i < E; i++) { g_offset[i] = s; s += g_count[i]; }
    }
}

// ---------------- GEMM1: 3-stage pipeline (R15-proven, byte-identical) --------
__global__ void __launch_bounds__(256, 2) gemm1_kernel(const float* __restrict__ w13) {
    extern __shared__ __align__(16) char smd[];
    __shared__ int s_tok[128];
    int e   = blockIdx.z;
    int cnt = g_count[e];
    int m0  = blockIdx.y * 128;
    if (m0 >= cnt) return;
    int n0  = blockIdx.x * 64;
    int off = g_offset[e];
    int tid = threadIdx.x, wid = tid >> 5, lane = tid & 31;

    if (tid < 128) {
        int m = m0 + tid;
        s_tok[tid] = g_tokens[e][(m < cnt) ? m : (cnt - 1)];
    }
    __syncthreads();

    int arow = tid >> 1, akh = tid & 1;
    const __nv_bfloat16* aHsrc = g_x_hi + (size_t)s_tok[arow] * D + akh * 8;
    const __nv_bfloat16* aLsrc = g_x_lo + (size_t)s_tok[arow] * D + akh * 8;
    uint32_t a_off = (uint32_t)(arow * ARS + akh * 16);
    int brow = tid >> 4, bc = tid & 15;
    int c8 = bc * 8;
    int ncol = (c8 < 64) ? (n0 + c8) : (MOED + n0 + (c8 - 64));
    const float* bptr = w13 + ((size_t)e * D + brow) * (2 * MOED) + ncol;
    uint32_t b_sdst = (uint32_t)(BH_OFF + brow * BRS + bc * 16);

    float accg[2][4][4], accu[2][4][4];
    #pragma unroll
    for (int i = 0; i < 2; i++)
        #pragma unroll
        for (int j = 0; j < 4; j++)
            #pragma unroll
            for (int q = 0; q < 4; q++) { accg[i][j][q] = 0.0f; accu[i][j][q] = 0.0f; }

    int wm = wid >> 1, wn = wid & 1;
    int lr = lane & 15, lh16 = (lane >> 4) << 4;
    int btr = ((lane >> 3) & 1) * 8 + (lane & 7);
    uint32_t sb = smem_u32(smd);

    float4 stgB[2];

    cpasync16(sb + a_off, aHsrc);
    cpasync16(sb + a_off + AL_OFF, aLsrc);
    CP_COMMIT();
    cpasync16(sb + STAGE + a_off, aHsrc + BK);
    cpasync16(sb + STAGE + a_off + AL_OFF, aLsrc + BK);
    CP_COMMIT();
    stgB[0] = *reinterpret_cast<const float4*>(bptr);
    stgB[1] = *reinterpret_cast<const float4*>(bptr + 4);
    {
        uint4 hi, lo;
        cvt8(stgB[0], stgB[1], hi, lo);
        *reinterpret_cast<uint4*>(smd + b_sdst) = hi;
        *reinterpret_cast<uint4*>(smd + b_sdst + (BL_OFF - BH_OFF)) = lo;
    }
    stgB[0] = *reinterpret_cast<const float4*>(bptr + (size_t)BK * (2 * MOED));
    stgB[1] = *reinterpret_cast<const float4*>(bptr + (size_t)BK * (2 * MOED) + 4);
    CP_WAIT1();
    __syncthreads();

    const int KT = D / BK;   // 64
    int cur = 0;
    for (int kt = 0; kt < KT; kt++) {
        int nx1 = cur + 1; if (nx1 >= 3) nx1 -= 3;
        int nx2 = cur + 2; if (nx2 >= 3) nx2 -= 3;

        if (kt + 2 < KT) {
            cpasync16(sb + nx2 * STAGE + a_off, aHsrc + (kt + 2) * BK);
            cpasync16(sb + nx2 * STAGE + a_off + AL_OFF, aLsrc + (kt + 2) * BK);
        }
        CP_COMMIT();
        if (kt + 1 < KT) {
            uint4 hi, lo;
            cvt8(stgB[0], stgB[1], hi, lo);
            *reinterpret_cast<uint4*>(smd + nx1 * STAGE + b_sdst) = hi;
            *reinterpret_cast<uint4*>(smd + nx1 * STAGE + b_sdst + (BL_OFF - BH_OFF)) = lo;
        }
        if (kt + 2 < KT) {
            stgB[0] = *reinterpret_cast<const float4*>(bptr + (size_t)(kt + 2) * BK * (2 * MOED));
            stgB[1] = *reinterpret_cast<const float4*>(bptr + (size_t)(kt + 2) * BK * (2 * MOED) + 4);
        }

        uint32_t bb = sb + cur * STAGE;
        uint32_t aH = bb + (uint32_t)(wm * 32 + lr) * ARS + lh16;
        uint32_t aL = aH + AL_OFF;
        uint32_t bH = bb + BH_OFF + (uint32_t)btr * BRS + wn * 64 + lh16;
        uint32_t bL = bH + (BL_OFF - BH_OFF);

        uint32_t ah[2][4], al[2][4];
        #pragma unroll
        for (int mi = 0; mi < 2; mi++) {
            ldsm4(ah[mi], aH + mi * (16 * ARS));
            ldsm4(al[mi], aL + mi * (16 * ARS));
        }
        #pragma unroll
        for (int half = 0; half < 2; half++) {
            uint32_t gh[4], gl[4], uh[4], ul[4];
            uint32_t boff = (uint32_t)(half * 32);
            ldsm4t(gh, bH + boff);
            ldsm4t(gl, bL + boff);
            ldsm4t(uh, bH + boff + 128);
            ldsm4t(ul, bL + boff + 128);
            #pragma unroll
            for (int r = 0; r < 2; r++) {
                int ni = half * 2 + r;
                #pragma unroll
                for (int mi = 0; mi < 2; mi++) {
                    mma16816(accg[mi][ni], ah[mi], gh[2 * r], gh[2 * r + 1]);
                    mma16816(accg[mi][ni], ah[mi], gl[2 * r], gl[2 * r + 1]);
                    mma16816(accg[mi][ni], al[mi], gh[2 * r], gh[2 * r + 1]);
                    mma16816(accu[mi][ni], ah[mi], uh[2 * r], uh[2 * r + 1]);
                    mma16816(accu[mi][ni], ah[mi], ul[2 * r], ul[2 * r + 1]);
                    mma16816(accu[mi][ni], al[mi], uh[2 * r], uh[2 * r + 1]);
                }
            }
        }
        CP_WAIT1();
        __syncthreads();
        cur = nx1;
    }

    #pragma unroll
    for (int mi = 0; mi < 2; mi++) {
        #pragma unroll
        for (int rr = 0; rr < 2; rr++) {
            int ml = wm * 32 + mi * 16 + (lane >> 2) + rr * 8;
            if (m0 + ml < cnt) {
                size_t rb = (size_t)(off + m0 + ml) * MOED + n0 + wn * 32;
                #pragma unroll
                for (int ni = 0; ni < 4; ni++) {
                    int nc = ni * 8 + (lane & 3) * 2;
                    float g0 = accg[mi][ni][rr * 2 + 0], g1 = accg[mi][ni][rr * 2 + 1];
                    float u0 = accu[mi][ni][rr * 2 + 0], u1 = accu[mi][ni][rr * 2 + 1];
                    float h0 = u0 * g0 / (1.0f + __expf(-g0));
                    float h1 = u1 * g1 / (1.0f + __expf(-g1));
                    uint32_t lo;
                    uint32_t hi = pack2(h0, h1, lo);
                    *reinterpret_cast<uint32_t*>(g_hid_hi + rb + nc) = hi;
                    *reinterpret_cast<uint32_t*>(g_hid_lo + rb + nc) = lo;
                }
            }
        }
    }
}

// ---------------- GEMM2: 4-stage ring, barrier every 2 stages -----------------
__global__ void __launch_bounds__(256, 2) gemm2_kernel(float* __restrict__ out) {
    extern __shared__ __align__(16) char smd[];
    int e   = blockIdx.z;
    int cnt = g_count[e];
    int m0  = blockIdx.y * 128;
    if (m0 >= cnt) return;
    int n0  = blockIdx.x * 128;
    int off = g_offset[e];
    int tid = threadIdx.x, wid = tid >> 5, lane = tid & 31;

    int arow = tid >> 1, akh = tid & 1;
    const __nv_bfloat16* aHsrc = g_hid_hi + (size_t)(off + m0 + arow) * MOED + akh * 8;
    const __nv_bfloat16* aLsrc = g_hid_lo + (size_t)(off + m0 + arow) * MOED + akh * 8;
    uint32_t a_off = (uint32_t)(arow * ARS + akh * 16);
    int brow = tid >> 4, bc = tid & 15;
    const __nv_bfloat16* bHsrc = g_w2_hi + ((size_t)e * MOED + brow) * D + n0 + bc * 8;
    const __nv_bfloat16* bLsrc = g_w2_lo + ((size_t)e * MOED + brow) * D + n0 + bc * 8;
    uint32_t b_off = (uint32_t)(BH_OFF + brow * BRS + bc * 16);

    float acc[2][8][4];
    #pragma unroll
    for (int i = 0; i < 2; i++)
        #pragma unroll
        for (int j = 0; j < 8; j++)
            #pragma unroll
            for (int q = 0; q < 4; q++) acc[i][j][q] = 0.0f;

    int wm = wid >> 1, wn = wid & 1;
    int lr = lane & 15, lh16 = (lane >> 4) << 4;
    int btr = ((lane >> 3) & 1) * 8 + (lane & 7);
    uint32_t sb = smem_u32(smd);

    auto load_stage = [&](int buf, size_t kb) {
        uint32_t sd = sb + buf * STAGE;
        cpasync16(sd + a_off, aHsrc + kb);
        cpasync16(sd + a_off + AL_OFF, aLsrc + kb);
        cpasync16(sd + b_off, bHsrc + kb * D);
        cpasync16(sd + b_off + (BL_OFF - BH_OFF), bLsrc + kb * D);
    };

    auto compute_stage = [&](int buf) {
        uint32_t bb = sb + buf * STAGE;
        uint32_t aH = bb + (uint32_t)(wm * 32 + lr) * ARS + lh16;
        uint32_t aL = aH + AL_OFF;
        uint32_t bH = bb + BH_OFF + (uint32_t)btr * BRS + wn * 128 + lh16;
        uint32_t bL = bH + (BL_OFF - BH_OFF);

        uint32_t ah[2][4], al[2][4];
        #pragma unroll
        for (int mi = 0; mi < 2; mi++) {
            ldsm4(ah[mi], aH + mi * (16 * ARS));
            ldsm4(al[mi], aL + mi * (16 * ARS));
        }
        #pragma unroll
        for (int half = 0; half < 4; half++) {
            uint32_t bh[4], bl[4];
            uint32_t boff = (uint32_t)(half * 32);
            ldsm4t(bh, bH + boff);
            ldsm4t(bl, bL + boff);
            #pragma unroll
            for (int r = 0; r < 2; r++) {
                int ni = half * 2 + r;
                #pragma unroll
                for (int mi = 0; mi < 2; mi++) {
                    mma16816(acc[mi][ni], ah[mi], bh[2 * r], bh[2 * r + 1]);
                    mma16816(acc[mi][ni], ah[mi], bl[2 * r], bl[2 * r + 1]);
                    mma16816(acc[mi][ni], al[mi], bh[2 * r], bh[2 * r + 1]);
                }
            }
        }
    };

    // prologue: stages 0,1
    load_stage(0, 0);
    load_stage(1, BK);
    CP_COMMIT();
    CP_WAIT0();
    __syncthreads();

    const int KT = MOED / BK;   // 128 (even)
    for (int kt = 0; kt < KT; kt += 2) {
        // issue loads for stages kt+2, kt+3 (land before next iteration's reads)
        if (kt + 2 < KT) load_stage((kt + 2) & 3, (size_t)(kt + 2) * BK);
        if (kt + 3 < KT) load_stage((kt + 3) & 3, (size_t)(kt + 3) * BK);
        CP_COMMIT();

        compute_stage(kt & 3);
        compute_stage((kt + 1) & 3);

        CP_WAIT0();
        __syncthreads();
    }

    // epilogue: weighted scatter-add (exactly 2 adds per out element)
    #pragma unroll
    for (int mi = 0; mi < 2; mi++) {
        #pragma unroll
        for (int rr = 0; rr < 2; rr++) {
            int ml = wm * 32 + mi * 16 + (lane >> 2) + rr * 8;
            if (m0 + ml < cnt) {
                int   t = g_tokens[e][m0 + ml];
                float w = g_weights[e][m0 + ml];
                float* orow = out + (size_t)t * D;
                #pragma unroll
                for (int ni = 0; ni < 8; ni++) {
                    int nc = n0 + wn * 64 + ni * 8 + (lane & 3) * 2;
                    atomicAdd(orow + nc,     w * acc[mi][ni][rr * 2 + 0]);
                    atomicAdd(orow + nc + 1, w * acc[mi][ni][rr * 2 + 1]);
                }
            }
        }
    }
}

// ---------------- launch ----------------
extern "C" void kernel_launch(void* const* d_in, const int* in_sizes, int n_in,
                              void* d_out, int out_size) {
    const float* x      = (const float*)d_in[0];
    const float* router = (const float*)d_in[1];
    const float* w13    = (const float*)d_in[2];
    const float* w2     = (const float*)d_in[3];
    float* out = (float*)d_out;

    int T = in_sizes[0] / D;   // 8192

    cudaFuncSetAttribute(gemm1_kernel, cudaFuncAttributeMaxDynamicSharedMemorySize, SM_G1);
    cudaFuncSetAttribute(gemm2_kernel, cudaFuncAttributeMaxDynamicSharedMemorySize, SM_G2);

    init_kernel<<<1024, 256>>>(out, out_size);
    w2split_kernel<<<(unsigned)((size_t)E * MOED * D / 8 / 256), 256>>>(w2);
    router_kernel<<<(T + 7) / 8, 256>>>(x, router, T);
    offsets_kernel<<<1, 32>>>();

    int mt = MAXCNT / 128;   // 32
    gemm1_kernel<<<dim3(MOED / 64, mt, E), 256, SM_G1>>>(w13);
    gemm2_kernel<<<dim3(D / 128, mt, E), 256, SM_G2>>>(out);
}

// round 17
// speedup vs baseline: 1.0183x; 1.0183x over previous
#include <cuda_runtime.h>
#include <cuda_bf16.h>
#include <math.h>
#include <stdint.h>

// ---------------- problem constants ----------------
#define D        1024
#define E        8
#define MOED     2048
#define T_TOK    8192
#define MAXROWS  16384
#define PADROWS  (MAXROWS + 256)
#define MAXCNT   4096

#define BK       16
#define ARS      48
#define BRS      272
#define AH_OFF   0
#define AL_OFF   6144
#define BH_OFF   12288
#define BL_OFF   16640
#define STAGE    20992
#define NSTG     3
#define SM_DYN   (NSTG * STAGE)   // 62976 dynamic, 2 CTAs = 126 KB

// ---------------- device scratch (~238 MB total; proven safe) ----------
__device__ int   g_count[E];
__device__ int   g_tokens[E][MAXROWS];
__device__ float g_weights[E][MAXROWS];
__device__ __align__(256) __nv_bfloat16 g_x_hi[(size_t)T_TOK * D];
__device__ __align__(256) __nv_bfloat16 g_x_lo[(size_t)T_TOK * D];
__device__ __align__(256) __nv_bfloat16 g_hid_hi[(size_t)PADROWS * MOED];
__device__ __align__(256) __nv_bfloat16 g_hid_lo[(size_t)PADROWS * MOED];
__device__ __align__(256) __nv_bfloat16 g_w2_hi[(size_t)E * MOED * D];
__device__ __align__(256) __nv_bfloat16 g_w2_lo[(size_t)E * MOED * D];

// ---------------- helpers ----------------
__device__ __forceinline__ uint32_t smem_u32(const void* p) {
    uint32_t a;
    asm("{ .reg .u64 t; cvta.to.shared.u64 t, %1; cvt.u32.u64 %0, t; }" : "=r"(a) : "l"(p));
    return a;
}
__device__ __forceinline__ void cpasync16(uint32_t s, const void* g) {
    asm volatile("cp.async.cg.shared.global [%0], [%1], 16;" :: "r"(s), "l"(g));
}
#define CP_COMMIT() asm volatile("cp.async.commit_group;" ::: "memory")
#define CP_WAIT1()  asm volatile("cp.async.wait_group 1;"  ::: "memory")

__device__ __forceinline__ void ldsm4(uint32_t* r, uint32_t addr) {
    asm volatile("ldmatrix.sync.aligned.m8n8.x4.shared.b16 {%0,%1,%2,%3}, [%4];"
        : "=r"(r[0]), "=r"(r[1]), "=r"(r[2]), "=r"(r[3]) : "r"(addr));
}
__device__ __forceinline__ void ldsm4t(uint32_t* r, uint32_t addr) {
    asm volatile("ldmatrix.sync.aligned.m8n8.x4.trans.shared.b16 {%0,%1,%2,%3}, [%4];"
        : "=r"(r[0]), "=r"(r[1]), "=r"(r[2]), "=r"(r[3]) : "r"(addr));
}
__device__ __forceinline__ void mma16816(float* c, const uint32_t* a, uint32_t b0, uint32_t b1) {
    asm volatile("mma.sync.aligned.m16n8k16.row.col.f32.bf16.bf16.f32 "
        "{%0,%1,%2,%3}, {%4,%5,%6,%7}, {%8,%9}, {%0,%1,%2,%3};"
        : "+f"(c[0]), "+f"(c[1]), "+f"(c[2]), "+f"(c[3])
        : "r"(a[0]), "r"(a[1]), "r"(a[2]), "r"(a[3]), "r"(b0), "r"(b1));
}
__device__ __forceinline__ uint32_t pack2(float a, float b, uint32_t& lo) {
    __nv_bfloat16 ha = __float2bfloat16(a);
    __nv_bfloat16 hb = __float2bfloat16(b);
    __nv_bfloat16 la = __float2bfloat16(a - __bfloat162float(ha));
    __nv_bfloat16 lb = __float2bfloat16(b - __bfloat162float(hb));
    lo = (uint32_t)__bfloat16_as_ushort(la) | ((uint32_t)__bfloat16_as_ushort(lb) << 16);
    return (uint32_t)__bfloat16_as_ushort(ha) | ((uint32_t)__bfloat16_as_ushort(hb) << 16);
}
__device__ __forceinline__ void cvt8(float4 v0, float4 v1, uint4& hi, uint4& lo) {
    uint32_t l0, l1, l2, l3;
    uint32_t h0 = pack2(v0.x, v0.y, l0);
    uint32_t h1 = pack2(v0.z, v0.w, l1);
    uint32_t h2 = pack2(v1.x, v1.y, l2);
    uint32_t h3 = pack2(v1.z, v1.w, l3);
    hi = make_uint4(h0, h1, h2, h3);
    lo = make_uint4(l0, l1, l2, l3);
}
__device__ __forceinline__ int expert_offset(int e) {
    int s = 0;
    #pragma unroll
    for (int i = 0; i < E; i++) if (i < e) s += g_count[i];
    return s;
}

// ---------------- fused init (zero out + counts) + w2 split -------------------
// blocks [0, ZB): zero out + counts; blocks [ZB, ZB+WB): w2 split
#define ZB 1024
__global__ void prep_kernel(const float* __restrict__ w2, float* __restrict__ out, int n) {
    if (blockIdx.x < ZB) {
        int i = blockIdx.x * blockDim.x + threadIdx.x;
        if (i < E) g_count[i] = 0;
        for (; i < n; i += ZB * blockDim.x) out[i] = 0.0f;
    } else {
        size_t i = ((size_t)(blockIdx.x - ZB) * blockDim.x + threadIdx.x) * 8;
        float4 v0 = *reinterpret_cast<const float4*>(w2 + i);
        float4 v1 = *reinterpret_cast<const float4*>(w2 + i + 4);
        uint4 hi, lo;
        cvt8(v0, v1, hi, lo);
        *reinterpret_cast<uint4*>(g_w2_hi + i) = hi;
        *reinterpret_cast<uint4*>(g_w2_lo + i) = lo;
    }
}

// ---------------- fused router + x split (R13-proven) ----------
__global__ void router_kernel(const float* __restrict__ x,
                              const float* __restrict__ router, int T) {
    __shared__ float s_r[D * E];
    int tid = threadIdx.x;
    for (int i = tid; i < D * E; i += 256) s_r[i] = router[i];
    __syncthreads();

    int warp = tid >> 5, lane = tid & 31;
    int t = blockIdx.x * 8 + warp;
    if (t >= T) return;

    const float4* xr = reinterpret_cast<const float4*>(x + (size_t)t * D);
    uint2* dh = reinterpret_cast<uint2*>(g_x_hi + (size_t)t * D);
    uint2* dl = reinterpret_cast<uint2*>(g_x_lo + (size_t)t * D);

    float acc[8];
    #pragma unroll
    for (int e = 0; e < 8; e++) acc[e] = 0.0f;

    #pragma unroll
    for (int i = 0; i < 8; i++) {
        int idx = i * 32 + lane;
        float4 v = xr[idx];
        uint32_t lo0, lo1;
        uint32_t h0 = pack2(v.x, v.y, lo0);
        uint32_t h1 = pack2(v.z, v.w, lo1);
        dh[idx] = make_uint2(h0, h1);
        dl[idx] = make_uint2(lo0, lo1);
        int k0 = idx * 4;
        float xv[4] = {v.x, v.y, v.z, v.w};
        #pragma unroll
        for (int j = 0; j < 4; j++) {
            const float4* r4 = reinterpret_cast<const float4*>(s_r + (k0 + j) * E);
            float4 r0 = r4[0], r1 = r4[1];
            acc[0] = fmaf(xv[j], r0.x, acc[0]);
            acc[1] = fmaf(xv[j], r0.y, acc[1]);
            acc[2] = fmaf(xv[j], r0.z, acc[2]);
            acc[3] = fmaf(xv[j], r0.w, acc[3]);
            acc[4] = fmaf(xv[j], r1.x, acc[4]);
            acc[5] = fmaf(xv[j], r1.y, acc[5]);
            acc[6] = fmaf(xv[j], r1.z, acc[6]);
            acc[7] = fmaf(xv[j], r1.w, acc[7]);
        }
    }
    #pragma unroll
    for (int e = 0; e < 8; e++) {
        #pragma unroll
        for (int s = 16; s > 0; s >>= 1)
            acc[e] += __shfl_xor_sync(0xFFFFFFFFu, acc[e], s);
    }
    if (lane == 0) {
        int e0 = 0; float l0 = acc[0];
        #pragma unroll
        for (int i = 1; i < E; i++) if (acc[i] > l0) { l0 = acc[i]; e0 = i; }
        int e1 = -1; float l1 = -INFINITY;
        #pragma unroll
        for (int i = 0; i < E; i++) {
            if (i == e0) continue;
            if (acc[i] > l1) { l1 = acc[i]; e1 = i; }
        }
        float w0 = 1.0f / (1.0f + expf(l1 - l0));
        float w1 = 1.0f - w0;
        int s0 = atomicAdd(&g_count[e0], 1);
        g_tokens[e0][s0]  = t;
        g_weights[e0][s0] = w0;
        int s1 = atomicAdd(&g_count[e1], 1);
        g_tokens[e1][s1]  = t;
        g_weights[e1][s1] = w1;
    }
}

// ---------------- GEMM1: 3-stage pipeline (R15-proven) --------
__global__ void __launch_bounds__(256, 2) gemm1_kernel(const float* __restrict__ w13) {
    extern __shared__ __align__(16) char smd[];
    __shared__ int s_tok[128];
    int e   = blockIdx.z;
    int cnt = g_count[e];
    int m0  = blockIdx.y * 128;
    if (m0 >= cnt) return;
    int n0  = blockIdx.x * 64;
    int off = expert_offset(e);
    int tid = threadIdx.x, wid = tid >> 5, lane = tid & 31;

    if (tid < 128) {
        int m = m0 + tid;
        s_tok[tid] = g_tokens[e][(m < cnt) ? m : (cnt - 1)];
    }
    __syncthreads();

    int arow = tid >> 1, akh = tid & 1;
    const __nv_bfloat16* aHsrc = g_x_hi + (size_t)s_tok[arow] * D + akh * 8;
    const __nv_bfloat16* aLsrc = g_x_lo + (size_t)s_tok[arow] * D + akh * 8;
    uint32_t a_off = (uint32_t)(arow * ARS + akh * 16);
    int brow = tid >> 4, bc = tid & 15;
    int c8 = bc * 8;
    int ncol = (c8 < 64) ? (n0 + c8) : (MOED + n0 + (c8 - 64));
    const float* bptr = w13 + ((size_t)e * D + brow) * (2 * MOED) + ncol;
    uint32_t b_sdst = (uint32_t)(BH_OFF + brow * BRS + bc * 16);

    float accg[2][4][4], accu[2][4][4];
    #pragma unroll
    for (int i = 0; i < 2; i++)
        #pragma unroll
        for (int j = 0; j < 4; j++)
            #pragma unroll
            for (int q = 0; q < 4; q++) { accg[i][j][q] = 0.0f; accu[i][j][q] = 0.0f; }

    int wm = wid >> 1, wn = wid & 1;
    int lr = lane & 15, lh16 = (lane >> 4) << 4;
    int btr = ((lane >> 3) & 1) * 8 + (lane & 7);
    uint32_t sb = smem_u32(smd);

    float4 stgB[2];

    cpasync16(sb + a_off, aHsrc);
    cpasync16(sb + a_off + AL_OFF, aLsrc);
    CP_COMMIT();
    cpasync16(sb + STAGE + a_off, aHsrc + BK);
    cpasync16(sb + STAGE + a_off + AL_OFF, aLsrc + BK);
    CP_COMMIT();
    stgB[0] = *reinterpret_cast<const float4*>(bptr);
    stgB[1] = *reinterpret_cast<const float4*>(bptr + 4);
    {
        uint4 hi, lo;
        cvt8(stgB[0], stgB[1], hi, lo);
        *reinterpret_cast<uint4*>(smd + b_sdst) = hi;
        *reinterpret_cast<uint4*>(smd + b_sdst + (BL_OFF - BH_OFF)) = lo;
    }
    stgB[0] = *reinterpret_cast<const float4*>(bptr + (size_t)BK * (2 * MOED));
    stgB[1] = *reinterpret_cast<const float4*>(bptr + (size_t)BK * (2 * MOED) + 4);
    CP_WAIT1();
    __syncthreads();

    const int KT = D / BK;   // 64
    int cur = 0;
    for (int kt = 0; kt < KT; kt++) {
        int nx1 = cur + 1; if (nx1 >= NSTG) nx1 -= NSTG;
        int nx2 = cur + 2; if (nx2 >= NSTG) nx2 -= NSTG;

        if (kt + 2 < KT) {
            cpasync16(sb + nx2 * STAGE + a_off, aHsrc + (kt + 2) * BK);
            cpasync16(sb + nx2 * STAGE + a_off + AL_OFF, aLsrc + (kt + 2) * BK);
        }
        CP_COMMIT();
        if (kt + 1 < KT) {
            uint4 hi, lo;
            cvt8(stgB[0], stgB[1], hi, lo);
            *reinterpret_cast<uint4*>(smd + nx1 * STAGE + b_sdst) = hi;
            *reinterpret_cast<uint4*>(smd + nx1 * STAGE + b_sdst + (BL_OFF - BH_OFF)) = lo;
        }
        if (kt + 2 < KT) {
            stgB[0] = *reinterpret_cast<const float4*>(bptr + (size_t)(kt + 2) * BK * (2 * MOED));
            stgB[1] = *reinterpret_cast<const float4*>(bptr + (size_t)(kt + 2) * BK * (2 * MOED) + 4);
        }

        uint32_t bb = sb + cur * STAGE;
        uint32_t aH = bb + (uint32_t)(wm * 32 + lr) * ARS + lh16;
        uint32_t aL = aH + AL_OFF;
        uint32_t bH = bb + BH_OFF + (uint32_t)btr * BRS + wn * 64 + lh16;
        uint32_t bL = bH + (BL_OFF - BH_OFF);

        uint32_t ah[2][4], al[2][4];
        #pragma unroll
        for (int mi = 0; mi < 2; mi++) {
            ldsm4(ah[mi], aH + mi * (16 * ARS));
            ldsm4(al[mi], aL + mi * (16 * ARS));
        }
        #pragma unroll
        for (int half = 0; half < 2; half++) {
            uint32_t gh[4], gl[4], uh[4], ul[4];
            uint32_t boff = (uint32_t)(half * 32);
            ldsm4t(gh, bH + boff);
            ldsm4t(gl, bL + boff);
            ldsm4t(uh, bH + boff + 128);
            ldsm4t(ul, bL + boff + 128);
            #pragma unroll
            for (int r = 0; r < 2; r++) {
                int ni = half * 2 + r;
                #pragma unroll
                for (int mi = 0; mi < 2; mi++) {
                    mma16816(accg[mi][ni], ah[mi], gh[2 * r], gh[2 * r + 1]);
                    mma16816(accg[mi][ni], ah[mi], gl[2 * r], gl[2 * r + 1]);
                    mma16816(accg[mi][ni], al[mi], gh[2 * r], gh[2 * r + 1]);
                    mma16816(accu[mi][ni], ah[mi], uh[2 * r], uh[2 * r + 1]);
                    mma16816(accu[mi][ni], ah[mi], ul[2 * r], ul[2 * r + 1]);
                    mma16816(accu[mi][ni], al[mi], uh[2 * r], uh[2 * r + 1]);
                }
            }
        }
        CP_WAIT1();
        __syncthreads();
        cur = nx1;
    }

    #pragma unroll
    for (int mi = 0; mi < 2; mi++) {
        #pragma unroll
        for (int rr = 0; rr < 2; rr++) {
            int ml = wm * 32 + mi * 16 + (lane >> 2) + rr * 8;
            if (m0 + ml < cnt) {
                size_t rb = (size_t)(off + m0 + ml) * MOED + n0 + wn * 32;
                #pragma unroll
                for (int ni = 0; ni < 4; ni++) {
                    int nc = ni * 8 + (lane & 3) * 2;
                    float g0 = accg[mi][ni][rr * 2 + 0], g1 = accg[mi][ni][rr * 2 + 1];
                    float u0 = accu[mi][ni][rr * 2 + 0], u1 = accu[mi][ni][rr * 2 + 1];
                    float h0 = u0 * g0 / (1.0f + __expf(-g0));
                    float h1 = u1 * g1 / (1.0f + __expf(-g1));
                    uint32_t lo;
                    uint32_t hi = pack2(h0, h1, lo);
                    *reinterpret_cast<uint32_t*>(g_hid_hi + rb + nc) = hi;
                    *reinterpret_cast<uint32_t*>(g_hid_lo + rb + nc) = lo;
                }
            }
        }
    }
}

// ---------------- GEMM2: 3-stage pipeline (R15-proven) ----------------
__global__ void __launch_bounds__(256, 2) gemm2_kernel(float* __restrict__ out) {
    extern __shared__ __align__(16) char smd[];
    int e   = blockIdx.z;
    int cnt = g_count[e];
    int m0  = blockIdx.y * 128;
    if (m0 >= cnt) return;
    int n0  = blockIdx.x * 128;
    int off = expert_offset(e);
    int tid = threadIdx.x, wid = tid >> 5, lane = tid & 31;

    int arow = tid >> 1, akh = tid & 1;
    const __nv_bfloat16* aHsrc = g_hid_hi + (size_t)(off + m0 + arow) * MOED + akh * 8;
    const __nv_bfloat16* aLsrc = g_hid_lo + (size_t)(off + m0 + arow) * MOED + akh * 8;
    uint32_t a_off = (uint32_t)(arow * ARS + akh * 16);
    int brow = tid >> 4, bc = tid & 15;
    const __nv_bfloat16* bHsrc = g_w2_hi + ((size_t)e * MOED + brow) * D + n0 + bc * 8;
    const __nv_bfloat16* bLsrc = g_w2_lo + ((size_t)e * MOED + brow) * D + n0 + bc * 8;
    uint32_t b_off = (uint32_t)(BH_OFF + brow * BRS + bc * 16);

    float acc[2][8][4];
    #pragma unroll
    for (int i = 0; i < 2; i++)
        #pragma unroll
        for (int j = 0; j < 8; j++)
            #pragma unroll
            for (int q = 0; q < 4; q++) acc[i][j][q] = 0.0f;

    int wm = wid >> 1, wn = wid & 1;
    int lr = lane & 15, lh16 = (lane >> 4) << 4;
    int btr = ((lane >> 3) & 1) * 8 + (lane & 7);
    uint32_t sb = smem_u32(smd);

    auto load_stage = [&](int buf, size_t kb) {
        uint32_t sd = sb + buf * STAGE;
        cpasync16(sd + a_off, aHsrc + kb);
        cpasync16(sd + a_off + AL_OFF, aLsrc + kb);
        cpasync16(sd + b_off, bHsrc + kb * D);
        cpasync16(sd + b_off + (BL_OFF - BH_OFF), bLsrc + kb * D);
    };

    load_stage(0, 0);
    CP_COMMIT();
    load_stage(1, BK);
    CP_COMMIT();
    CP_WAIT1();
    __syncthreads();

    const int KT = MOED / BK;   // 128
    int cur = 0;
    for (int kt = 0; kt < KT; kt++) {
        int nx1 = cur + 1; if (nx1 >= NSTG) nx1 -= NSTG;
        int nx2 = cur + 2; if (nx2 >= NSTG) nx2 -= NSTG;

        if (kt + 2 < KT) load_stage(nx2, (size_t)(kt + 2) * BK);
        CP_COMMIT();

        uint32_t bb = sb + cur * STAGE;
        uint32_t aH = bb + (uint32_t)(wm * 32 + lr) * ARS + lh16;
        uint32_t aL = aH + AL_OFF;
        uint32_t bH = bb + BH_OFF + (uint32_t)btr * BRS + wn * 128 + lh16;
        uint32_t bL = bH + (BL_OFF - BH_OFF);

        uint32_t ah[2][4], al[2][4];
        #pragma unroll
        for (int mi = 0; mi < 2; mi++) {
            ldsm4(ah[mi], aH + mi * (16 * ARS));
            ldsm4(al[mi], aL + mi * (16 * ARS));
        }
        #pragma unroll
        for (int half = 0; half < 4; half++) {
            uint32_t bh[4], bl[4];
            uint32_t boff = (uint32_t)(half * 32);
            ldsm4t(bh, bH + boff);
            ldsm4t(bl, bL + boff);
            #pragma unroll
            for (int r = 0; r < 2; r++) {
                int ni = half * 2 + r;
                #pragma unroll
                for (int mi = 0; mi < 2; mi++) {
                    mma16816(acc[mi][ni], ah[mi], bh[2 * r], bh[2 * r + 1]);
                    mma16816(acc[mi][ni], ah[mi], bl[2 * r], bl[2 * r + 1]);
                    mma16816(acc[mi][ni], al[mi], bh[2 * r], bh[2 * r + 1]);
                }
            }
        }
        CP_WAIT1();
        __syncthreads();
        cur = nx1;
    }

    #pragma unroll
    for (int mi = 0; mi < 2; mi++) {
        #pragma unroll
        for (int rr = 0; rr < 2; rr++) {
            int ml = wm * 32 + mi * 16 + (lane >> 2) + rr * 8;
            if (m0 + ml < cnt) {
                int   t = g_tokens[e][m0 + ml];
                float w = g_weights[e][m0 + ml];
                float* orow = out + (size_t)t * D;
                #pragma unroll
                for (int ni = 0; ni < 8; ni++) {
                    int nc = n0 + wn * 64 + ni * 8 + (lane & 3) * 2;
                    atomicAdd(orow + nc,     w * acc[mi][ni][rr * 2 + 0]);
                    atomicAdd(orow + nc + 1, w * acc[mi][ni][rr * 2 + 1]);
                }
            }
        }
    }
}

// ---------------- launch ----------------
extern "C" void kernel_launch(void* const* d_in, const int* in_sizes, int n_in,
                              void* d_out, int out_size) {
    const float* x      = (const float*)d_in[0];
    const float* router = (const float*)d_in[1];
    const float* w13    = (const float*)d_in[2];
    const float* w2     = (const float*)d_in[3];
    float* out = (float*)d_out;

    int T = in_sizes[0] / D;   // 8192

    cudaFuncSetAttribute(gemm1_kernel, cudaFuncAttributeMaxDynamicSharedMemorySize, SM_DYN);
    cudaFuncSetAttribute(gemm2_kernel, cudaFuncAttributeMaxDynamicSharedMemorySize, SM_DYN);

    unsigned wb = (unsigned)((size_t)E * MOED * D / 8 / 256);   // 8192 split blocks
    prep_kernel<<<ZB + wb, 256>>>(w2, out, out_size);
    router_kernel<<<(T + 7) / 8, 256>>>(x, router, T);

    int mt = MAXCNT / 128;   // 32
    gemm1_kernel<<<dim3(MOED / 64, mt, E), 256, SM_DYN>>>(w13);
    gemm2_kernel<<<dim3(D / 128, mt, E), 256, SM_DYN>>>(out);
}